// round 3
// baseline (speedup 1.0000x reference)
#include <cuda_runtime.h>

// FeatNeighbourCorr, R3: barrier-free register-streaming kernel.
// out[b,k,h,w] = <n_p, n_{p-d_k}>, n = feats/||feats||_C, reflect pad d=1.
// Offsets k: (1,0)(1,1)(0,1)(-1,1)(-1,0)(-1,-1)(0,-1)(1,-1) -> neighbor (h-dx, w-dy).
// Each warp: 4 output rows x 64 cols; lane owns a w-pair (f32x2).
// w-neighbors via shfl; warp-boundary cols via 2 predicated scalar loads/row.

#define HH 256
#define WW 256
#define CC 128
#define HW (HH * WW)
#define RB 4                 // output rows per band
#define JR (RB + 2)          // staged rows (with halo) = 6
#define BANDS (HH / RB)      // 64
#define NTHREADS 128         // 4 warps = 4 w-spans of 64 cols

typedef unsigned long long u64;

__device__ __forceinline__ u64 pack2(float lo, float hi) {
    u64 r;
    asm("mov.b64 %0, {%1,%2};" : "=l"(r) : "f"(lo), "f"(hi));
    return r;
}
__device__ __forceinline__ float lo2(u64 a) { return __uint_as_float((unsigned)a); }
__device__ __forceinline__ float hi2(u64 a) { return __uint_as_float((unsigned)(a >> 32)); }
__device__ __forceinline__ void fma2(u64& d, u64 a, u64 b) {
    asm("fma.rn.f32x2 %0, %1, %2, %0;" : "+l"(d) : "l"(a), "l"(b));
}
__device__ __forceinline__ u64 mul2(u64 a, u64 b) {
    u64 r;
    asm("mul.rn.f32x2 %0, %1, %2;" : "=l"(r) : "l"(a), "l"(b));
    return r;
}

__global__ __launch_bounds__(NTHREADS, 3)
void featcorr_r3_kernel(const float* __restrict__ feats, float* __restrict__ out) {
    const int lane = threadIdx.x & 31;
    const int span = threadIdx.x >> 5;          // 0..3, 64 cols each
    const int cta  = blockIdx.x;
    const int b    = cta >> 6;
    const int band = cta & 63;
    const int h0   = band * RB;
    const int col  = span * 64 + lane * 2;

    const bool halo0  = (lane == 0);
    const bool halo31 = (lane == 31);
    // scalar halo column offset relative to own pair base (in floats)
    const int hoff = halo0 ? ((span == 0) ? 1 : -1)
                           : ((span == 3) ? 0 : 2);

    // row element-offsets (reflect in h)
    int o[JR];
#pragma unroll
    for (int j = 0; j < JR; ++j) {
        int gh = h0 - 1 + j;
        gh = (gh < 0) ? -gh : ((gh > HH - 1) ? 2 * (HH - 1) - gh : gh);
        o[j] = gh * WW + col;
    }

    const float* bp = feats + (size_t)b * CC * HW;

    u64 acc[RB][8];
#pragma unroll
    for (int r = 0; r < RB; ++r)
#pragma unroll
        for (int k = 0; k < 8; ++k) acc[r][k] = 0ull;
    u64 ssqC[JR];
    float hssq[JR], hv[JR];
#pragma unroll
    for (int j = 0; j < JR; ++j) { ssqC[j] = 0ull; hssq[j] = 0.f; hv[j] = 0.f; }

    for (int c = 0; c < CC; ++c) {
        u64 v[JR];
#pragma unroll
        for (int j = 0; j < JR; ++j)
            v[j] = __ldg(reinterpret_cast<const u64*>(bp + o[j]));

        if (halo0 || halo31) {
#pragma unroll
            for (int j = 0; j < JR; ++j) {
                float x = __ldg(bp + o[j] + hoff);
                hv[j] = x;
                hssq[j] += x * x;
            }
        }

        u64 L[JR], Rt[JR];
#pragma unroll
        for (int j = 0; j < JR; ++j) {
            float vx = lo2(v[j]), vy = hi2(v[j]);
            float tl = __shfl_up_sync(0xffffffffu, vy, 1);
            float ly = halo0 ? hv[j] : tl;
            float tr = __shfl_down_sync(0xffffffffu, vx, 1);
            float rx = halo31 ? hv[j] : tr;
            L[j]  = pack2(ly, vx);
            Rt[j] = pack2(vy, rx);
            fma2(ssqC[j], v[j], v[j]);
        }

#pragma unroll
        for (int j = 1; j <= RB; ++j) {
            const u64 cv = v[j];
            fma2(acc[j - 1][0], cv, v[j - 1]);   // ( 1, 0)
            fma2(acc[j - 1][1], cv, L[j - 1]);   // ( 1, 1)
            fma2(acc[j - 1][2], cv, L[j]);       // ( 0, 1)
            fma2(acc[j - 1][3], cv, L[j + 1]);   // (-1, 1)
            fma2(acc[j - 1][4], cv, v[j + 1]);   // (-1, 0)
            fma2(acc[j - 1][5], cv, Rt[j + 1]);  // (-1,-1)
            fma2(acc[j - 1][6], cv, Rt[j]);      // ( 0,-1)
            fma2(acc[j - 1][7], cv, Rt[j - 1]);  // ( 1,-1)
        }

        bp += HW;
    }

    // ---- norms ----
    float rnx[JR], rny[JR], hrn[JR];
#pragma unroll
    for (int j = 0; j < JR; ++j) {
        rnx[j] = rsqrtf(lo2(ssqC[j]));
        rny[j] = rsqrtf(hi2(ssqC[j]));
        hrn[j] = rsqrtf(hssq[j]);    // valid on halo lanes only
    }
    u64 rnC[JR], rnL[JR], rnR[JR];
#pragma unroll
    for (int j = 0; j < JR; ++j) {
        float tl = __shfl_up_sync(0xffffffffu, rny[j], 1);
        float ly = halo0 ? hrn[j] : tl;
        float tr = __shfl_down_sync(0xffffffffu, rnx[j], 1);
        float rx = halo31 ? hrn[j] : tr;
        rnC[j] = pack2(rnx[j], rny[j]);
        rnL[j] = pack2(ly, rnx[j]);
        rnR[j] = pack2(rny[j], rx);
    }

    // ---- apply norms and store ----
    float* ob = out + ((size_t)b * 8) * HW;
#pragma unroll
    for (int j = 1; j <= RB; ++j) {
        const int h = h0 + j - 1;
        const u64 rc = rnC[j];
        u64 nb[8] = {rnC[j - 1], rnL[j - 1], rnL[j], rnL[j + 1],
                     rnC[j + 1], rnR[j + 1], rnR[j], rnR[j - 1]};
#pragma unroll
        for (int k = 0; k < 8; ++k) {
            u64 val = mul2(mul2(acc[j - 1][k], rc), nb[k]);
            *reinterpret_cast<u64*>(ob + (size_t)k * HW + (size_t)h * WW + col) = val;
        }
    }
}

extern "C" void kernel_launch(void* const* d_in, const int* in_sizes, int n_in,
                              void* d_out, int out_size) {
    const float* feats = (const float*)d_in[0];
    float* out = (float*)d_out;
    featcorr_r3_kernel<<<8 * BANDS, NTHREADS>>>(feats, out);
}

// round 6
// speedup vs baseline: 1.0088x; 1.0088x over previous
#include <cuda_runtime.h>

// FeatNeighbourCorr R4: 4-directional Gram maps + gather epilogue.
// out_k(p) = G_d(r) * rn(p) * rn(q);  G_d(r) = sum_c f(r) f(r+d),
// d in {A=(0,1), B=(1,0), C=(1,1), D=(1,-1)}; q = reflect(p - d_k).

#define HH 256
#define WW 256
#define CC 128
#define HW (HH * WW)
#define TH 32
#define TW 32
#define SROWS 34              // staged rows: h0-1 .. h0+32
#define SP2   18              // staged float2 per row: cols w0-2 .. w0+33
#define SSTR2 19              // padded float2 stride
#define SSTRF (SSTR2 * 2)     // 38 floats
#define NSLOT_ST (SROWS * SP2)   // 612
#define GROWS 33              // G rows: h0-1 .. h0+31
#define GPAIRS 17             // G col pairs: cols rel 0..33
#define GSTRF 36              // padded float stride (even)
#define GPLANE (GROWS * GSTRF)   // 1188 floats per direction
#define NSLOT_G (GROWS * GPAIRS) // 561
#define NTHREADS 256
#define POOLF (4 * GPLANE + SROWS * SSTR2 * 2)  // 4752 + 1292 = 6044 floats

typedef unsigned long long u64;

__device__ __forceinline__ u64 pack2(float lo, float hi) {
    u64 r; asm("mov.b64 %0, {%1,%2};" : "=l"(r) : "f"(lo), "f"(hi)); return r;
}
__device__ __forceinline__ float lo2(u64 a) { return __uint_as_float((unsigned)a); }
__device__ __forceinline__ float hi2(u64 a) { return __uint_as_float((unsigned)(a >> 32)); }
__device__ __forceinline__ void fma2(u64& d, u64 a, u64 b) {
    asm("fma.rn.f32x2 %0, %1, %2, %0;" : "+l"(d) : "l"(a), "l"(b));
}
__device__ __forceinline__ int refl(int x) {
    return x < 0 ? -x : (x > HH - 1 ? 2 * (HH - 1) - x : x);
}

__global__ __launch_bounds__(NTHREADS, 3)
void featcorr_r4(const float* __restrict__ feats, float* __restrict__ out) {
    __shared__ float pool[POOLF];
    const int t  = threadIdx.x;
    const int b  = blockIdx.z;
    const int h0 = blockIdx.y * TH;
    const int w0 = blockIdx.x * TW;

    // ---- stage slots (f tile 34x36, float2 granularity) ----
    int goff0[3], goff1[3], soff[3]; bool sv[3];
#pragma unroll
    for (int u = 0; u < 3; ++u) {
        int s = t + 256 * u; sv[u] = s < NSLOT_ST;
        int ss = sv[u] ? s : 0;
        int row = ss / SP2, pc = ss - row * SP2;
        int gh = refl(h0 - 1 + row);
        int c0 = w0 - 2 + 2 * pc;
        goff0[u] = gh * WW + refl(c0);
        goff1[u] = gh * WW + refl(c0 + 1);
        soff[u]  = row * SSTR2 + pc;
    }
    // ---- G slots (33 rows x 17 pairs) ----
    int p0off[3], gdoff[3]; bool gv[3];
#pragma unroll
    for (int u = 0; u < 3; ++u) {
        int s = t + 256 * u; gv[u] = s < NSLOT_G;
        int ss = gv[u] ? s : 0;
        int j = ss / GPAIRS, pr = ss - j * GPAIRS;
        p0off[u] = j * SSTR2 + pr;           // float2 index into stage buffer
        gdoff[u] = j * (GSTRF / 2) + pr;     // float2 index into G plane
    }

    u64 gA[3], gB[3], gC[3], gD[3];
#pragma unroll
    for (int u = 0; u < 3; ++u) { gA[u] = gB[u] = gC[u] = gD[u] = 0ull; }
    float ssx[3] = {0.f, 0.f, 0.f}, ssy[3] = {0.f, 0.f, 0.f};

    const float* gp = feats + (size_t)b * CC * HW;
    float rx[3], ry[3];
#pragma unroll
    for (int u = 0; u < 3; ++u) {
        rx[u] = sv[u] ? __ldg(gp + goff0[u]) : 0.f;
        ry[u] = sv[u] ? __ldg(gp + goff1[u]) : 0.f;
    }

    float2* bufb = (float2*)pool;
    u64*    bufu = (u64*)pool;

    for (int ch = 0; ch < CC; ++ch) {
        float2* bw = bufb + (ch & 1) * (SROWS * SSTR2);
#pragma unroll
        for (int u = 0; u < 3; ++u)
            if (sv[u]) bw[soff[u]] = make_float2(rx[u], ry[u]);
#pragma unroll
        for (int u = 0; u < 3; ++u) { ssx[u] += rx[u] * rx[u]; ssy[u] += ry[u] * ry[u]; }
        if (ch + 1 < CC) {
            gp += HW;
#pragma unroll
            for (int u = 0; u < 3; ++u)
                if (sv[u]) { rx[u] = __ldg(gp + goff0[u]); ry[u] = __ldg(gp + goff1[u]); }
        }
        __syncthreads();
        const u64* br = bufu + (ch & 1) * (SROWS * SSTR2);
#pragma unroll
        for (int u = 0; u < 3; ++u) {
            if (gv[u]) {
                u64 P0 = br[p0off[u]],          P1 = br[p0off[u] + 1];
                u64 Q0 = br[p0off[u] + SSTR2],  Q1 = br[p0off[u] + SSTR2 + 1];
                u64 Cw = pack2(hi2(P0), lo2(P1));   // f(r), f(r+w)
                u64 Dw = pack2(hi2(Q0), lo2(Q1));   // f(r+h), f(r+h+w)
                fma2(gA[u], Cw, P1);   // (0,1)
                fma2(gB[u], Cw, Dw);   // (1,0)
                fma2(gC[u], Cw, Q1);   // (1,1)
                fma2(gD[u], Cw, Q0);   // (1,-1)
            }
        }
    }
    __syncthreads();   // protect G dump over stage buffers

    // ---- dump rn and G to smem ----
    float2* rn2 = (float2*)(pool + 4 * GPLANE);
#pragma unroll
    for (int u = 0; u < 3; ++u)
        if (sv[u]) rn2[soff[u]] = make_float2(rsqrtf(ssx[u]), rsqrtf(ssy[u]));
    float2* g2 = (float2*)pool;
#pragma unroll
    for (int u = 0; u < 3; ++u) {
        if (gv[u]) {
            g2[0 * (GPLANE / 2) + gdoff[u]] = make_float2(lo2(gA[u]), hi2(gA[u]));
            g2[1 * (GPLANE / 2) + gdoff[u]] = make_float2(lo2(gB[u]), hi2(gB[u]));
            g2[2 * (GPLANE / 2) + gdoff[u]] = make_float2(lo2(gC[u]), hi2(gC[u]));
            g2[3 * (GPLANE / 2) + gdoff[u]] = make_float2(lo2(gD[u]), hi2(gD[u]));
        }
    }
    __syncthreads();

    // ---- gather epilogue ----
    const float* Gs  = pool;
    const float* rnf = pool + 4 * GPLANE;
    const int oy = t >> 3, ox = (t & 7) << 2;
    const int h  = h0 + oy;
    float rp[4];
#pragma unroll
    for (int i = 0; i < 4; ++i) rp[i] = rnf[(oy + 1) * SSTRF + (ox + i + 2)];

    const int DXv[8] = {1, 1, 0, -1, -1, -1, 0, 1};
    const int DYv[8] = {0, 1, 1, 1, 0, -1, -1, -1};
    float* ob = out + ((size_t)b * 8) * HW + (size_t)h * WW + (w0 + ox);
#pragma unroll
    for (int k = 0; k < 8; ++k) {
        float v[4];
#pragma unroll
        for (int i = 0; i < 4; ++i) {
            int w  = w0 + ox + i;
            int qh = refl(h - DXv[k]);
            int qw = refl(w - DYv[k]);
            int dir, rh, rw;
            if (DXv[k] == 0)      { dir = 0; rh = h; rw = min(w, qw); }
            else if (DYv[k] == 0) { dir = 1; rh = min(h, qh); rw = w; }
            else {
                bool dn = qh > h;
                rh = dn ? h : qh;
                rw = dn ? w : qw;
                int dw = dn ? (qw - w) : (w - qw);
                dir = (dw == 1) ? 2 : 3;
            }
            float g  = Gs[dir * GPLANE + (rh - h0 + 1) * GSTRF + (rw - w0 + 1)];
            float rq = rnf[(qh - h0 + 1) * SSTRF + (qw - w0 + 2)];
            v[i] = g * rp[i] * rq;
        }
        float4 r4 = make_float4(v[0], v[1], v[2], v[3]);
        *reinterpret_cast<float4*>(ob + (size_t)k * HW) = r4;
    }
}

extern "C" void kernel_launch(void* const* d_in, const int* in_sizes, int n_in,
                              void* d_out, int out_size) {
    const float* feats = (const float*)d_in[0];
    float* out = (float*)d_out;
    dim3 grid(WW / TW, HH / TH, 8);
    featcorr_r4<<<grid, NTHREADS>>>(feats, out);
}

// round 8
// speedup vs baseline: 1.6877x; 1.6730x over previous
#include <cuda_runtime.h>

// FeatNeighbourCorr R5: cp.async(8B) double-buffered pipeline + f32x2 compute.
// out[b,k,h,w] = <n_p, n_q>, n = f/||f||_C, q = reflect(p - d_k).
// Tile 16(h) x 32(w), 128 threads, 4-channel chunks, 32 pipelined iterations.

#define HH 256
#define WW 256
#define CC 128
#define HW (HH * WW)
#define TH 16
#define TW 32
#define KC 4
#define NCH (CC / KC)        // 32 chunk iterations
#define SR 18                // staged rows  (h0-1 .. h0+16)
#define SPC 18               // staged float2 per row (cols w0-2 .. w0+33)
#define SSTR2 19             // padded float2 stride
#define PLANE2 (SR * SSTR2)  // 342 float2 per channel plane
#define BUF2 (KC * PLANE2)   // 1368 float2 per buffer
#define NSLOT (KC * SR * SPC) // 1296 cp slots
#define NT 128
#define RNSTR 35

typedef unsigned long long u64;

__device__ __forceinline__ u64 pack2(float lo, float hi) {
    u64 r; asm("mov.b64 %0, {%1,%2};" : "=l"(r) : "f"(lo), "f"(hi)); return r;
}
__device__ __forceinline__ float lo2(u64 a) { return __uint_as_float((unsigned)a); }
__device__ __forceinline__ float hi2(u64 a) { return __uint_as_float((unsigned)(a >> 32)); }
__device__ __forceinline__ void fma2(u64& d, u64 a, u64 b) {
    asm("fma.rn.f32x2 %0, %1, %2, %0;" : "+l"(d) : "l"(a), "l"(b));
}
__device__ __forceinline__ u64 mul2(u64 a, u64 b) {
    u64 r; asm("mul.rn.f32x2 %0, %1, %2;" : "=l"(r) : "l"(a), "l"(b)); return r;
}
__device__ __forceinline__ int refl(int x) {
    return x < 0 ? -x : (x > HH - 1 ? 2 * (HH - 1) - x : x);
}

__global__ __launch_bounds__(NT, 5)
void featcorr_r5(const float* __restrict__ feats, float* __restrict__ out) {
    __shared__ u64 pool[2 * BUF2];
    const int t  = threadIdx.x;
    const int b  = blockIdx.z;
    const int h0 = blockIdx.y * TH;
    const int w0 = blockIdx.x * TW;
    const unsigned sbase = (unsigned)__cvta_generic_to_shared(pool);

    // ---- cp.async slots over (ch, row, pc), chunk-invariant ----
    int src[11]; unsigned dst[11]; bool val[11];
#pragma unroll
    for (int u = 0; u < 11; ++u) {
        int s = t + NT * u;
        bool in = s < NSLOT;
        int ss = in ? s : 0;
        int ch = ss / (SR * SPC);
        int r  = ss - ch * (SR * SPC);
        int row = r / SPC, pc = r - row * SPC;
        int gh = refl(h0 - 1 + row);
        int gc = w0 - 2 + 2 * pc;
        bool edge = (gc < 0) || (gc >= WW - 1);   // pair straddles image border
        val[u] = in && !edge;
        src[u] = ch * HW + gh * WW + gc;
        dst[u] = sbase + (unsigned)((ch * PLANE2 + row * SSTR2 + pc) * 8);
    }

    // ---- scalar slots for reflected w-edge pairs (edge tiles only) ----
    const bool eact = (w0 == 0 || w0 == WW - TW) && (t < KC * SR);  // 72 threads
    int es0 = 0, es1 = 0, eidx = 0;
    if (eact) {
        int ch = t / SR, row = t - ch * SR;
        int gh = refl(h0 - 1 + row);
        if (w0 == 0) {  // pair (-2,-1) -> (f[2], f[1])
            es0 = ch * HW + gh * WW + 2;  es1 = es0 - 1;
            eidx = ch * PLANE2 + row * SSTR2 + 0;
        } else {        // pair (256,257) -> (f[254], f[253])
            es0 = ch * HW + gh * WW + 254; es1 = es0 - 1;
            eidx = ch * PLANE2 + row * SSTR2 + 17;
        }
    }

    // ---- halo-ring ssq slot (100 ring pixels) ----
    const bool ract = t < 100;
    int roff = 0, rnoff = 0;
    if (ract) {
        int rrow, rcol;
        if (t < 34)       { rrow = 0;       rcol = 1 + t; }
        else if (t < 68)  { rrow = SR - 1;  rcol = 1 + t - 34; }
        else if (t < 84)  { rrow = t - 67;  rcol = 1; }
        else              { rrow = t - 83;  rcol = 34; }
        roff  = rrow * (SSTR2 * 2) + rcol;   // float index within ch plane
        rnoff = rrow * RNSTR + rcol;
    }

    const int py = t >> 3, pxg = t & 7;
    const int sc0 = 2 * pxg;

    u64 acc0[8], acc1[8];
#pragma unroll
    for (int k = 0; k < 8; ++k) { acc0[k] = 0ull; acc1[k] = 0ull; }
    u64 ssq01 = 0ull, ssq23 = 0ull;
    float rss = 0.f;
    float ex = 0.f, ey = 0.f;

    const float* bp = feats + (size_t)b * CC * HW;

    // prologue: chunk 0
    {
        unsigned bo = 0;
#pragma unroll
        for (int u = 0; u < 11; ++u)
            if (val[u])
                asm volatile("cp.async.ca.shared.global [%0], [%1], 8;"
                             :: "r"(dst[u] + bo), "l"(bp + src[u]) : "memory");
        asm volatile("cp.async.commit_group;" ::: "memory");
        if (eact) { ex = __ldg(bp + es0); ey = __ldg(bp + es1); }
    }

    for (int it = 0; it < NCH; ++it) {
        asm volatile("cp.async.wait_group 0;" ::: "memory");
        if (eact)
            reinterpret_cast<float2*>(pool)[(it & 1) * BUF2 + eidx] = make_float2(ex, ey);
        __syncthreads();

        if (it + 1 < NCH) {
            const float* bn = bp + KC * HW;
            unsigned bo = (unsigned)(((it + 1) & 1) * BUF2 * 8);
#pragma unroll
            for (int u = 0; u < 11; ++u)
                if (val[u])
                    asm volatile("cp.async.ca.shared.global [%0], [%1], 8;"
                                 :: "r"(dst[u] + bo), "l"(bn + src[u]) : "memory");
            asm volatile("cp.async.commit_group;" ::: "memory");
            if (eact) { ex = __ldg(bn + es0); ey = __ldg(bn + es1); }
        }

        const u64* B = pool + (it & 1) * BUF2;
#pragma unroll
        for (int ch = 0; ch < KC; ++ch) {
            const u64* tp = B + ch * PLANE2 + py * SSTR2 + sc0;
            u64 t0 = tp[0], t1 = tp[1], t2 = tp[2], t3 = tp[3];
            const u64* mp = tp + SSTR2;
            u64 m0 = mp[0], m1 = mp[1], m2 = mp[2], m3 = mp[3];
            const u64* bq = mp + SSTR2;
            u64 b0 = bq[0], b1 = bq[1], b2 = bq[2], b3 = bq[3];

            u64 tL = pack2(hi2(t0), lo2(t1)), tM = pack2(hi2(t1), lo2(t2)), tR = pack2(hi2(t2), lo2(t3));
            u64 mL = pack2(hi2(m0), lo2(m1)), mM = pack2(hi2(m1), lo2(m2)), mR = pack2(hi2(m2), lo2(m3));
            u64 bL = pack2(hi2(b0), lo2(b1)), bM = pack2(hi2(b1), lo2(b2)), bR = pack2(hi2(b2), lo2(b3));

            fma2(acc0[0], m1, t1); fma2(acc0[1], m1, tL);
            fma2(acc0[2], m1, mL); fma2(acc0[3], m1, bL);
            fma2(acc0[4], m1, b1); fma2(acc0[5], m1, bM);
            fma2(acc0[6], m1, mM); fma2(acc0[7], m1, tM);

            fma2(acc1[0], m2, t2); fma2(acc1[1], m2, tM);
            fma2(acc1[2], m2, mM); fma2(acc1[3], m2, bM);
            fma2(acc1[4], m2, b2); fma2(acc1[5], m2, bR);
            fma2(acc1[6], m2, mR); fma2(acc1[7], m2, tR);

            fma2(ssq01, m1, m1);   fma2(ssq23, m2, m2);

            if (ract) {
                float rv = reinterpret_cast<const float*>(B)[ch * (PLANE2 * 2) + roff];
                rss += rv * rv;
            }
        }
        bp += KC * HW;
    }

    // ---- norms: centers in regs, ring via smem map (aliased over buffer 0) ----
    float rp0 = rsqrtf(lo2(ssq01)), rp1 = rsqrtf(hi2(ssq01));
    float rp2 = rsqrtf(lo2(ssq23)), rp3 = rsqrtf(hi2(ssq23));
    float* RN = reinterpret_cast<float*>(pool);   // 18 x 35 floats, fits in buf0
    {
        int cb = (py + 1) * RNSTR + sc0 * 2 + 2;
        RN[cb] = rp0; RN[cb + 1] = rp1; RN[cb + 2] = rp2; RN[cb + 3] = rp3;
    }
    if (ract) RN[rnoff] = rsqrtf(rss);
    __syncthreads();

    // ---- gather neighbor norms, scale, store float4 per offset ----
    const int DXa[8] = {1, 1, 0, -1, -1, -1, 0, 1};
    const int DYa[8] = {0, 1, 1, 1, 0, -1, -1, -1};
    const int h = h0 + py;
    const int wb = w0 + 4 * pxg;
    const u64 rp01 = pack2(rp0, rp1), rp23 = pack2(rp2, rp3);
    float* ob = out + ((size_t)b * 8) * HW + (size_t)h * WW + wb;
#pragma unroll
    for (int k = 0; k < 8; ++k) {
        int qsr = refl(h - DXa[k]) - (h0 - 1);
        float rq[4];
#pragma unroll
        for (int i = 0; i < 4; ++i) {
            int qw = refl(wb + i - DYa[k]);
            rq[i] = RN[qsr * RNSTR + (qw - w0 + 2)];
        }
        u64 o01 = mul2(mul2(acc0[k], rp01), pack2(rq[0], rq[1]));
        u64 o23 = mul2(mul2(acc1[k], rp23), pack2(rq[2], rq[3]));
        float4 v = make_float4(lo2(o01), hi2(o01), lo2(o23), hi2(o23));
        *reinterpret_cast<float4*>(ob + (size_t)k * HW) = v;
    }
}

extern "C" void kernel_launch(void* const* d_in, const int* in_sizes, int n_in,
                              void* d_out, int out_size) {
    const float* feats = (const float*)d_in[0];
    float* out = (float*)d_out;
    dim3 grid(WW / TW, HH / TH, 8);
    featcorr_r5<<<grid, NT>>>(feats, out);
}